// round 3
// baseline (speedup 1.0000x reference)
#include <cuda_runtime.h>

#define SEQ 512
#define CHAN 512
#define NH 8
#define BATCH 32
#define TP 64     // p-rows per block
#define TC 128    // channels per block
#define KC 16     // k-chunk
#define NTHREADS 256

// w table: wtab[delta][head], delta in Z8^3 packed as (d2<<6 | d1<<3 | d0)
__device__ __align__(16) float g_wtab[SEQ * NH];

__global__ void wtab_kernel(const float* __restrict__ basis,
                            const float* __restrict__ kern) {
    __shared__ float sk[24 * NH];
    int t = threadIdx.x;
    if (t < 24 * NH) sk[t] = kern[t];
    __syncthreads();
    if (t < SEQ) {
        float acc[NH];
#pragma unroll
        for (int h = 0; h < NH; h++) acc[h] = 0.f;
#pragma unroll
        for (int s = 0; s < 24; s++) {
            float bv = basis[t * 24 + s];
#pragma unroll
            for (int h = 0; h < NH; h++) acc[h] = fmaf(bv, sk[s * NH + h], acc[h]);
        }
#pragma unroll
        for (int h = 0; h < NH; h++) g_wtab[t * NH + h] = acc[h];
    }
}

// per-axis (p' - p) mod 8, packed back into a 9-bit group index (0..511)
__device__ __forceinline__ int delta_idx(int pp, int pr) {
    int d0 = (pp - pr) & 7;
    int d1 = ((pp >> 3) - (pr >> 3)) & 7;
    int d2 = ((pp >> 6) - (pr >> 6)) & 7;
    return (d2 << 6) | (d1 << 3) | d0;
}

__global__ __launch_bounds__(NTHREADS) void conv_kernel(
    const float* __restrict__ x, float* __restrict__ out) {
    __shared__ float4 s_w[SEQ * 2];        // wtab as float4 halves: [delta][h0..3],[h4..7] (16KB)
    __shared__ float4 s_x[KC * (TC / 4)];  // x tile [kk][ci]                                (8KB)
    __shared__ __align__(16) unsigned short s_d[KC * TP];  // 16-bit deltas [kk][row]        (2KB)

    const int tid  = threadIdx.x;
    const int lane = tid & 31;
    const int rg   = tid >> 5;          // row group 0..7
    const int r0   = rg * 8;            // first of this thread's 8 rows
    const int hsel = lane & 1;          // c0 = lane*4 -> heads {0..3} or {4..7}
    const int cbase = blockIdx.x * TC;
    const int pbase = blockIdx.y * TP;
    const int b     = blockIdx.z;

    // stage wtab into smem (read as float4 pairs)
    {
        const float4* gw = reinterpret_cast<const float4*>(g_wtab);
#pragma unroll
        for (int i = 0; i < (SEQ * 2) / NTHREADS; i++)
            s_w[tid + i * NTHREADS] = gw[tid + i * NTHREADS];
    }

    float4 acc[8];
#pragma unroll
    for (int i = 0; i < 8; i++) acc[i] = make_float4(0.f, 0.f, 0.f, 0.f);

    // x viewed as float4 rows, starting at (b, 0, cbase)
    const float4* xg = reinterpret_cast<const float4*>(
        x + (size_t)b * SEQ * CHAN + cbase);

    // ---- prefetch chunk 0 into registers ----
    float4 rx0, rx1;
    ushort4 rd;
    {
        int f0 = tid, f1 = tid + NTHREADS;
        rx0 = xg[(f0 >> 5) * (CHAN / 4) + (f0 & 31)];
        rx1 = xg[(f1 >> 5) * (CHAN / 4) + (f1 & 31)];
        int e  = tid * 4;
        int kk = e >> 6, rr = e & 63;
        int pp = kk;  // kb = 0
        rd.x = (unsigned short)delta_idx(pp, pbase + rr + 0);
        rd.y = (unsigned short)delta_idx(pp, pbase + rr + 1);
        rd.z = (unsigned short)delta_idx(pp, pbase + rr + 2);
        rd.w = (unsigned short)delta_idx(pp, pbase + rr + 3);
    }

    for (int kb = 0; kb < SEQ; kb += KC) {
        // commit staged chunk to smem
        {
            s_x[tid]            = rx0;
            s_x[tid + NTHREADS] = rx1;
            *reinterpret_cast<ushort4*>(&s_d[tid * 4]) = rd;
        }
        __syncthreads();

        // prefetch next chunk (overlaps with compute below)
        if (kb + KC < SEQ) {
            int kb2 = kb + KC;
            int f0 = tid, f1 = tid + NTHREADS;
            rx0 = xg[(kb2 + (f0 >> 5)) * (CHAN / 4) + (f0 & 31)];
            rx1 = xg[(kb2 + (f1 >> 5)) * (CHAN / 4) + (f1 & 31)];
            int e  = tid * 4;
            int kk = e >> 6, rr = e & 63;
            int pp = kb2 + kk;
            rd.x = (unsigned short)delta_idx(pp, pbase + rr + 0);
            rd.y = (unsigned short)delta_idx(pp, pbase + rr + 1);
            rd.z = (unsigned short)delta_idx(pp, pbase + rr + 2);
            rd.w = (unsigned short)delta_idx(pp, pbase + rr + 3);
        }

        // compute: 16 k-steps x 8 rows x 4 channels
#pragma unroll
        for (int kk = 0; kk < KC; kk++) {
            float4 xv = s_x[kk * 32 + lane];
            // 8 ushort deltas for rows r0..r0+7, one 16B aligned LDS
            uint4 dv = *reinterpret_cast<const uint4*>(&s_d[kk * TP + r0]);
            unsigned dw[4] = {dv.x, dv.y, dv.z, dv.w};
#pragma unroll
            for (int i = 0; i < 8; i++) {
                int dlt = (int)((dw[i >> 1] >> ((i & 1) * 16)) & 0xFFFFu);
                float4 wv = s_w[dlt * 2 + hsel];
                acc[i].x = fmaf(wv.x, xv.x, acc[i].x);
                acc[i].y = fmaf(wv.y, xv.y, acc[i].y);
                acc[i].z = fmaf(wv.z, xv.z, acc[i].z);
                acc[i].w = fmaf(wv.w, xv.w, acc[i].w);
            }
        }
        __syncthreads();
    }

    // epilogue: coalesced float4 stores
    float4* og = reinterpret_cast<float4*>(out + (size_t)b * SEQ * CHAN + cbase);
#pragma unroll
    for (int i = 0; i < 8; i++) {
        og[(pbase + r0 + i) * (CHAN / 4) + lane] = acc[i];
    }
}

extern "C" void kernel_launch(void* const* d_in, const int* in_sizes, int n_in,
                              void* d_out, int out_size) {
    // Dispatch inputs by element count — robust to any harness ordering.
    //   x: 32*512*512 = 8388608, basis: 512*24 = 12288, kernel: 24*8 = 192
    const float* x = nullptr;
    const float* basis = nullptr;
    const float* kern = nullptr;
    for (int i = 0; i < n_in; i++) {
        if (in_sizes[i] == BATCH * SEQ * CHAN)      x     = (const float*)d_in[i];
        else if (in_sizes[i] == SEQ * 24)           basis = (const float*)d_in[i];
        else if (in_sizes[i] == 24 * NH)            kern  = (const float*)d_in[i];
    }
    float* out = (float*)d_out;  // [32, 512, 512] f32

    wtab_kernel<<<1, 512>>>(basis, kern);
    dim3 grid(CHAN / TC, SEQ / TP, BATCH);        // (4, 8, 32)
    conv_kernel<<<grid, NTHREADS>>>(x, out);
}

// round 4
// speedup vs baseline: 2.2141x; 2.2141x over previous
#include <cuda_runtime.h>

#define SEQ 512
#define CHAN 512
#define NH 8
#define BATCH 32
#define TP 64     // p-rows per block
#define TC 128    // channels per block
#define KC 16     // k-chunk (two 8-groups)
#define NTHREADS 256

// packed fp32x2 FMA (SASS FFMA2) — only reachable via PTX
#define FMA_F32X2(acc, a, b) \
    asm("fma.rn.f32x2 %0, %1, %2, %0;" : "+l"(acc) : "l"(a), "l"(b))

// w table: wtab[delta][head], delta in Z8^3 packed as (d2<<6 | d1<<3 | d0)
__device__ __align__(16) float g_wtab[SEQ * NH];

__global__ void wtab_kernel(const float* __restrict__ basis,
                            const float* __restrict__ kern) {
    __shared__ float sk[24 * NH];
    int t = threadIdx.x;
    if (t < 24 * NH) sk[t] = kern[t];
    __syncthreads();
    if (t < SEQ) {
        float acc[NH];
#pragma unroll
        for (int h = 0; h < NH; h++) acc[h] = 0.f;
#pragma unroll
        for (int s = 0; s < 24; s++) {
            float bv = basis[t * 24 + s];
#pragma unroll
            for (int h = 0; h < NH; h++) acc[h] = fmaf(bv, sk[s * NH + h], acc[h]);
        }
#pragma unroll
        for (int h = 0; h < NH; h++) g_wtab[t * NH + h] = acc[h];
    }
}

__global__ __launch_bounds__(NTHREADS) void conv_kernel(
    const float* __restrict__ x, float* __restrict__ out) {
    __shared__ float4 s_w[SEQ * 2];        // wtab halves: [delta][h0..3],[h4..7] (16KB)
    __shared__ float4 s_x[KC * (TC / 4)];  // x tile [kk][ci]                      (8KB)

    const int tid  = threadIdx.x;
    const int lane = tid & 31;
    const int rg   = tid >> 5;          // row group 0..7
    const int r0   = rg * 8;            // first of this thread's 8 rows
    const int hsel = lane & 1;          // c0 = lane*4 -> heads {0..3} or {4..7}
    const int cbase = blockIdx.x * TC;
    const int pbase = blockIdx.y * TP;
    const int b     = blockIdx.z;

    // stage wtab into smem (first consumer is after the first __syncthreads)
    {
        const float4* gw = reinterpret_cast<const float4*>(g_wtab);
#pragma unroll
        for (int i = 0; i < (SEQ * 2) / NTHREADS; i++)
            s_w[tid + i * NTHREADS] = gw[tid + i * NTHREADS];
    }

    // packed accumulators: acc[i] = 4 channels of row r0+i as 2x f32x2
    ulonglong2 acc[8];
#pragma unroll
    for (int i = 0; i < 8; i++) { acc[i].x = 0ULL; acc[i].y = 0ULL; }

    // x viewed as float4 rows, starting at (b, 0, cbase)
    const float4* xg = reinterpret_cast<const float4*>(
        x + (size_t)b * SEQ * CHAN + cbase);

    // ---- prefetch chunk 0 into registers ----
    float4 rx0, rx1;
    {
        int f0 = tid, f1 = tid + NTHREADS;
        rx0 = xg[(f0 >> 5) * (CHAN / 4) + (f0 & 31)];
        rx1 = xg[(f1 >> 5) * (CHAN / 4) + (f1 & 31)];
    }

    // per-thread constant parts of the delta high bits
    const int pblk3 = (pbase + r0) >> 3;   // p's aligned 8-block
    const int pblk6 = pbase >> 6;          // p's aligned 64-block

    for (int kb = 0; kb < SEQ; kb += KC) {
        // commit staged chunk to smem
        s_x[tid]            = rx0;
        s_x[tid + NTHREADS] = rx1;
        __syncthreads();

        // prefetch next chunk (overlaps with compute below)
        if (kb + KC < SEQ) {
            int kb2 = kb + KC;
            int f0 = tid, f1 = tid + NTHREADS;
            rx0 = xg[(kb2 + (f0 >> 5)) * (CHAN / 4) + (f0 & 31)];
            rx1 = xg[(kb2 + (f1 >> 5)) * (CHAN / 4) + (f1 & 31)];
        }

        // two aligned 8-groups of p' per chunk
#pragma unroll
        for (int g = 0; g < 2; g++) {
            const int kgb = kb + g * 8;
            // delta high bits: identical for all (i,j) in this group
            const int d1 = ((kgb >> 3) - pblk3) & 7;
            const int d2 = ((kgb >> 6) - pblk6) & 7;
            const int base = (d2 << 6) | (d1 << 3);

            // load the full 8-entry w block into registers (warp-broadcast LDS)
            ulonglong2 wreg[8];
#pragma unroll
            for (int t = 0; t < 8; t++)
                wreg[t] = *reinterpret_cast<const ulonglong2*>(
                    &s_w[(base + t) * 2 + hsel]);

#pragma unroll
            for (int j = 0; j < 8; j++) {
                ulonglong2 xv = *reinterpret_cast<const ulonglong2*>(
                    &s_x[(g * 8 + j) * 32 + lane]);
#pragma unroll
                for (int i = 0; i < 8; i++) {
                    // d0 = (j - i) & 7 : compile-time register index
                    const int t = (j - i) & 7;
                    FMA_F32X2(acc[i].x, wreg[t].x, xv.x);
                    FMA_F32X2(acc[i].y, wreg[t].y, xv.y);
                }
            }
        }
        __syncthreads();
    }

    // epilogue: coalesced float4 stores
    float4* og = reinterpret_cast<float4*>(out + (size_t)b * SEQ * CHAN + cbase);
#pragma unroll
    for (int i = 0; i < 8; i++) {
        og[(pbase + r0 + i) * (CHAN / 4) + lane] =
            *reinterpret_cast<const float4*>(&acc[i]);
    }
}

extern "C" void kernel_launch(void* const* d_in, const int* in_sizes, int n_in,
                              void* d_out, int out_size) {
    // Dispatch inputs by element count — robust to any harness ordering.
    const float* x = nullptr;
    const float* basis = nullptr;
    const float* kern = nullptr;
    for (int i = 0; i < n_in; i++) {
        if (in_sizes[i] == BATCH * SEQ * CHAN)      x     = (const float*)d_in[i];
        else if (in_sizes[i] == SEQ * 24)           basis = (const float*)d_in[i];
        else if (in_sizes[i] == 24 * NH)            kern  = (const float*)d_in[i];
    }
    float* out = (float*)d_out;  // [32, 512, 512] f32

    wtab_kernel<<<1, 512>>>(basis, kern);
    dim3 grid(CHAN / TC, SEQ / TP, BATCH);        // (4, 8, 32)
    conv_kernel<<<grid, NTHREADS>>>(x, out);
}

// round 6
// speedup vs baseline: 2.8127x; 1.2704x over previous
#include <cuda_runtime.h>
#include <cuda_bf16.h>
#include <cstdint>

#define SEQ 512
#define CHAN 512
#define NH 8
#define BATCH 32
#define NPH 2048   // n per head = 32 batch * 64 ch

// ---------------- device globals (scratch; no allocs allowed) ----------------
__device__ __align__(16) float g_wtab[SEQ * NH];                 // [delta][h]
__device__ __align__(16) __nv_bfloat16 g_whi[NH * SEQ * SEQ];    // [h][p][p'] 4MB
__device__ __align__(16) __nv_bfloat16 g_wlo[NH * SEQ * SEQ];
__device__ __align__(16) __nv_bfloat16 g_xhi[NH * NPH * SEQ];    // [h][n][p'] 16MB
__device__ __align__(16) __nv_bfloat16 g_xlo[NH * NPH * SEQ];

// ---------------- helpers ----------------
__device__ __forceinline__ uint32_t smem_u32(const void* p) {
    uint32_t a;
    asm("{ .reg .u64 t; cvta.to.shared.u64 t, %1; cvt.u32.u64 %0, t; }" : "=r"(a) : "l"(p));
    return a;
}
__device__ __forceinline__ void ldsm_x4(uint32_t r[4], uint32_t addr) {
    asm volatile("ldmatrix.sync.aligned.m8n8.x4.shared.b16 {%0,%1,%2,%3}, [%4];"
                 : "=r"(r[0]), "=r"(r[1]), "=r"(r[2]), "=r"(r[3]) : "r"(addr));
}
__device__ __forceinline__ void mma_bf16(float c[4], const uint32_t a[4],
                                         const uint32_t* b) {
    asm volatile("mma.sync.aligned.m16n8k16.row.col.f32.bf16.bf16.f32 "
                 "{%0,%1,%2,%3}, {%4,%5,%6,%7}, {%8,%9}, {%0,%1,%2,%3};"
                 : "+f"(c[0]), "+f"(c[1]), "+f"(c[2]), "+f"(c[3])
                 : "r"(a[0]), "r"(a[1]), "r"(a[2]), "r"(a[3]), "r"(b[0]), "r"(b[1]));
}

// ---------------- kernel 1: wtab = basis @ kernel ----------------
__global__ void wtab_kernel(const float* __restrict__ basis,
                            const float* __restrict__ kern) {
    __shared__ float sk[24 * NH];
    int t = threadIdx.x;
    if (t < 24 * NH) sk[t] = kern[t];
    __syncthreads();
    if (t < SEQ) {
        float acc[NH];
#pragma unroll
        for (int h = 0; h < NH; h++) acc[h] = 0.f;
#pragma unroll
        for (int s = 0; s < 24; s++) {
            float bv = basis[t * 24 + s];
#pragma unroll
            for (int h = 0; h < NH; h++) acc[h] = fmaf(bv, sk[s * NH + h], acc[h]);
        }
#pragma unroll
        for (int h = 0; h < NH; h++) g_wtab[t * NH + h] = acc[h];
    }
}

__device__ __forceinline__ int delta_idx(int pp, int pr) {
    int d0 = (pp - pr) & 7;
    int d1 = ((pp >> 3) - (pr >> 3)) & 7;
    int d2 = ((pp >> 6) - (pr >> 6)) & 7;
    return (d2 << 6) | (d1 << 3) | d0;
}

// ---------------- kernel 2: materialize W_h hi/lo, [h][p][p'] ----------------
__global__ void wsplit_kernel() {
    int idx4 = (blockIdx.x * 256 + threadIdx.x) * 4;   // 8*512*512 total
    int h = idx4 >> 18;
    int rem = idx4 & 0x3FFFF;
    int p = rem >> 9;
    int pp0 = rem & 511;
    __align__(8) __nv_bfloat16 hb[4], lb[4];
#pragma unroll
    for (int j = 0; j < 4; j++) {
        float w = g_wtab[delta_idx(pp0 + j, p) * NH + h];
        __nv_bfloat16 hi = __float2bfloat16(w);
        hb[j] = hi;
        lb[j] = __float2bfloat16(w - __bfloat162float(hi));
    }
    *reinterpret_cast<uint2*>(&g_whi[idx4]) = *reinterpret_cast<uint2*>(hb);
    *reinterpret_cast<uint2*>(&g_wlo[idx4]) = *reinterpret_cast<uint2*>(lb);
}

// ---------------- kernel 3: x -> per-head K-major hi/lo, [h][n][p'] ----------------
__global__ __launch_bounds__(256) void xsplit_kernel(const float* __restrict__ x) {
    __shared__ float s[64][65];
    const int t = threadIdx.x;
    const int c0 = blockIdx.x * 64;
    const int p0 = blockIdx.y * 64;
    const int b  = blockIdx.z;

#pragma unroll
    for (int it = 0; it < 16; it++) {
        int prow = it * 4 + (t >> 6);
        int cl   = t & 63;
        s[prow][cl] = x[((size_t)(b * SEQ) + p0 + prow) * CHAN + c0 + cl];
    }
    __syncthreads();

    const int cl = t >> 2;
    const int pq = t & 3;
    const int c  = c0 + cl;
    const int h  = c & 7;
    const int ch = c >> 3;
    const size_t base = ((size_t)(h * NPH) + b * 64 + ch) * SEQ + p0 + pq * 16;
    __align__(16) __nv_bfloat16 hb[16], lb[16];
#pragma unroll
    for (int k = 0; k < 16; k++) {
        float v = s[pq * 16 + k][cl];
        __nv_bfloat16 hi = __float2bfloat16(v);
        hb[k] = hi;
        lb[k] = __float2bfloat16(v - __bfloat162float(hi));
    }
    *reinterpret_cast<uint4*>(&g_xhi[base])     = *reinterpret_cast<uint4*>(hb);
    *reinterpret_cast<uint4*>(&g_xhi[base + 8]) = *reinterpret_cast<uint4*>(hb + 8);
    *reinterpret_cast<uint4*>(&g_xlo[base])     = *reinterpret_cast<uint4*>(lb);
    *reinterpret_cast<uint4*>(&g_xlo[base + 8]) = *reinterpret_cast<uint4*>(lb + 8);
}

// ---------------- kernel 4: HMMA GEMM, writes out directly ----------------
// CTA: (ptile 128, head, batch). Warps 4x2: each M=32, N=32, K=512 in 8 chunks.
// smem (48KB static): Ahi 16K | Alo 16K | Bhi 8K | Blo 8K, XOR-16B swizzled rows.
#define AHI 0
#define ALO 16384
#define BHI 32768
#define BLO 40960

__global__ __launch_bounds__(256, 2) void gemm_kernel(float* __restrict__ out) {
    __shared__ __align__(16) unsigned char sm[49152];
    const uint32_t sb = smem_u32(sm);
    const int tid  = threadIdx.x;
    const int lane = tid & 31;
    const int wid  = tid >> 5;
    const int wm   = wid & 3;       // m-group: 32 p rows
    const int wn   = wid >> 2;      // n-group: 32 ch cols
    const int p0 = blockIdx.x * 128;
    const int h  = blockIdx.y;
    const int b  = blockIdx.z;

    const __nv_bfloat16* gAhi = g_whi + ((size_t)h * SEQ + p0) * SEQ;
    const __nv_bfloat16* gAlo = g_wlo + ((size_t)h * SEQ + p0) * SEQ;
    const __nv_bfloat16* gBhi = g_xhi + ((size_t)h * NPH + b * 64) * SEQ;
    const __nv_bfloat16* gBlo = g_xlo + ((size_t)h * NPH + b * 64) * SEQ;

    // ldmatrix per-lane bases: groups of 8 lanes pick the four 8x8 matrices
    const int g  = lane >> 3, rr = lane & 7;
    const int a_row = wm * 32 + (g & 1) * 8 + rr;    // + mi*16
    const int a_cg  = g >> 1;                        // + 2*ks
    const int b_row = wn * 32 + (g >> 1) * 8 + rr;   // + nt*16
    const int b_cg  = g & 1;                         // + 2*ks

    float acc[2][4][4];
#pragma unroll
    for (int mi = 0; mi < 2; mi++)
#pragma unroll
        for (int ni = 0; ni < 4; ni++)
#pragma unroll
            for (int e = 0; e < 4; e++) acc[mi][ni][e] = 0.f;

    for (int ck = 0; ck < 8; ck++) {
        const int kb = ck * 64;
        __syncthreads();
        // stage A: 128 rows x 8 vec16 per half
#pragma unroll
        for (int i = 0; i < 4; i++) {
            int vid = tid + i * 256;
            int row = vid >> 3, c16 = vid & 7;
            int so = (row * 8 + (c16 ^ (row & 7))) * 16;
            *(uint4*)(sm + AHI + so) =
                *(const uint4*)(gAhi + (size_t)row * SEQ + kb + c16 * 8);
            *(uint4*)(sm + ALO + so) =
                *(const uint4*)(gAlo + (size_t)row * SEQ + kb + c16 * 8);
        }
        // stage B: 64 rows x 8 vec16 per half
#pragma unroll
        for (int i = 0; i < 2; i++) {
            int vid = tid + i * 256;
            int row = vid >> 3, c16 = vid & 7;
            int so = (row * 8 + (c16 ^ (row & 7))) * 16;
            *(uint4*)(sm + BHI + so) =
                *(const uint4*)(gBhi + (size_t)row * SEQ + kb + c16 * 8);
            *(uint4*)(sm + BLO + so) =
                *(const uint4*)(gBlo + (size_t)row * SEQ + kb + c16 * 8);
        }
        __syncthreads();

#pragma unroll
        for (int ks = 0; ks < 4; ks++) {
            uint32_t Ah[2][4], Al[2][4], Bh[2][4], Bl[2][4];
#pragma unroll
            for (int mi = 0; mi < 2; mi++) {
                int row = a_row + mi * 16;
                int c16 = 2 * ks + a_cg;
                uint32_t ad = sb + (uint32_t)((row * 8 + (c16 ^ (row & 7))) * 16);
                ldsm_x4(Ah[mi], ad + AHI);
                ldsm_x4(Al[mi], ad + ALO);
            }
#pragma unroll
            for (int nt = 0; nt < 2; nt++) {
                int row = b_row + nt * 16;
                int c16 = 2 * ks + b_cg;
                uint32_t bd = sb + (uint32_t)((row * 8 + (c16 ^ (row & 7))) * 16);
                ldsm_x4(Bh[nt], bd + BHI);
                ldsm_x4(Bl[nt], bd + BLO);
            }
#pragma unroll
            for (int mi = 0; mi < 2; mi++)
#pragma unroll
                for (int ni = 0; ni < 4; ni++) {
                    const uint32_t* bh = &Bh[ni >> 1][(ni & 1) * 2];
                    const uint32_t* bl = &Bl[ni >> 1][(ni & 1) * 2];
                    mma_bf16(acc[mi][ni], Ah[mi], bh);  // hi*hi
                    mma_bf16(acc[mi][ni], Ah[mi], bl);  // hi*lo
                    mma_bf16(acc[mi][ni], Al[mi], bh);  // lo*hi
                }
        }
    }

    // epilogue: C frag (row = lane/4 (+8), col = 2*(lane%4)+{0,1}) -> out[b][p][ch*8+h]
    const int prb = p0 + wm * 32 + (lane >> 2);
    const int chb = wn * 32 + 2 * (lane & 3);
    float* ob = out + (size_t)b * SEQ * CHAN + h;
#pragma unroll
    for (int mi = 0; mi < 2; mi++)
#pragma unroll
        for (int ni = 0; ni < 4; ni++)
#pragma unroll
            for (int e = 0; e < 4; e++) {
                int p  = prb + mi * 16 + (e >> 1) * 8;
                int ch = chb + ni * 8 + (e & 1);
                ob[(size_t)p * CHAN + ch * NH] = acc[mi][ni][e];
            }
}

// ---------------- launch ----------------
extern "C" void kernel_launch(void* const* d_in, const int* in_sizes, int n_in,
                              void* d_out, int out_size) {
    const float* x = nullptr;
    const float* basis = nullptr;
    const float* kern = nullptr;
    for (int i = 0; i < n_in; i++) {
        if (in_sizes[i] == BATCH * SEQ * CHAN)      x     = (const float*)d_in[i];
        else if (in_sizes[i] == SEQ * 24)           basis = (const float*)d_in[i];
        else if (in_sizes[i] == 24 * NH)            kern  = (const float*)d_in[i];
    }
    float* out = (float*)d_out;

    wtab_kernel<<<1, 512>>>(basis, kern);
    wsplit_kernel<<<2048, 256>>>();
    xsplit_kernel<<<dim3(8, 8, 32), 256>>>(x);
    gemm_kernel<<<dim3(4, NH, BATCH), 256>>>(out);
}

// round 7
// speedup vs baseline: 3.1242x; 1.1107x over previous
#include <cuda_runtime.h>
#include <cuda_bf16.h>
#include <cstdint>

#define SEQ 512
#define CHAN 512
#define NH 8
#define BATCH 32
#define NPH 2048   // n per head = 32 batch * 64 ch

// ---------------- device globals (scratch; no allocs allowed) ----------------
__device__ __align__(16) float g_wtab[SEQ * NH];                 // [delta][h]
__device__ __align__(16) __nv_bfloat16 g_whi[NH * SEQ * SEQ];    // [h][p][p'] 4MB
__device__ __align__(16) __nv_bfloat16 g_wlo[NH * SEQ * SEQ];
__device__ __align__(16) __nv_bfloat16 g_xhi[NH * NPH * SEQ];    // [h][n][p'] 16MB
__device__ __align__(16) __nv_bfloat16 g_xlo[NH * NPH * SEQ];

// ---------------- helpers ----------------
__device__ __forceinline__ uint32_t smem_u32(const void* p) {
    uint32_t a;
    asm("{ .reg .u64 t; cvta.to.shared.u64 t, %1; cvt.u32.u64 %0, t; }" : "=r"(a) : "l"(p));
    return a;
}
__device__ __forceinline__ void ldsm_x4(uint32_t r[4], uint32_t addr) {
    asm volatile("ldmatrix.sync.aligned.m8n8.x4.shared.b16 {%0,%1,%2,%3}, [%4];"
                 : "=r"(r[0]), "=r"(r[1]), "=r"(r[2]), "=r"(r[3]) : "r"(addr));
}
__device__ __forceinline__ void mma_bf16(float c[4], const uint32_t a[4],
                                         const uint32_t* b) {
    asm volatile("mma.sync.aligned.m16n8k16.row.col.f32.bf16.bf16.f32 "
                 "{%0,%1,%2,%3}, {%4,%5,%6,%7}, {%8,%9}, {%0,%1,%2,%3};"
                 : "+f"(c[0]), "+f"(c[1]), "+f"(c[2]), "+f"(c[3])
                 : "r"(a[0]), "r"(a[1]), "r"(a[2]), "r"(a[3]), "r"(b[0]), "r"(b[1]));
}
#define CP_ASYNC16(dst, src) \
    asm volatile("cp.async.cg.shared.global [%0], [%1], 16;" \
                 :: "r"(dst), "l"(src) : "memory")
#define CP_COMMIT() asm volatile("cp.async.commit_group;" ::: "memory")
#define CP_WAIT(n)  asm volatile("cp.async.wait_group %0;" :: "n"(n) : "memory")

// ---------------- kernel 1: wtab = basis @ kernel ----------------
__global__ void wtab_kernel(const float* __restrict__ basis,
                            const float* __restrict__ kern) {
    __shared__ float sk[24 * NH];
    int t = threadIdx.x;
    if (t < 24 * NH) sk[t] = kern[t];
    __syncthreads();
    if (t < SEQ) {
        float acc[NH];
#pragma unroll
        for (int h = 0; h < NH; h++) acc[h] = 0.f;
#pragma unroll
        for (int s = 0; s < 24; s++) {
            float bv = basis[t * 24 + s];
#pragma unroll
            for (int h = 0; h < NH; h++) acc[h] = fmaf(bv, sk[s * NH + h], acc[h]);
        }
#pragma unroll
        for (int h = 0; h < NH; h++) g_wtab[t * NH + h] = acc[h];
    }
}

__device__ __forceinline__ int delta_idx(int pp, int pr) {
    int d0 = (pp - pr) & 7;
    int d1 = ((pp >> 3) - (pr >> 3)) & 7;
    int d2 = ((pp >> 6) - (pr >> 6)) & 7;
    return (d2 << 6) | (d1 << 3) | d0;
}

// ---------------- kernel 2: materialize W_h hi/lo, [h][p][p'] ----------------
__global__ void wsplit_kernel() {
    int idx4 = (blockIdx.x * 256 + threadIdx.x) * 4;   // 8*512*512 total
    int h = idx4 >> 18;
    int rem = idx4 & 0x3FFFF;
    int p = rem >> 9;
    int pp0 = rem & 511;
    __align__(8) __nv_bfloat16 hb[4], lb[4];
#pragma unroll
    for (int j = 0; j < 4; j++) {
        float w = g_wtab[delta_idx(pp0 + j, p) * NH + h];
        __nv_bfloat16 hi = __float2bfloat16(w);
        hb[j] = hi;
        lb[j] = __float2bfloat16(w - __bfloat162float(hi));
    }
    *reinterpret_cast<uint2*>(&g_whi[idx4]) = *reinterpret_cast<uint2*>(hb);
    *reinterpret_cast<uint2*>(&g_wlo[idx4]) = *reinterpret_cast<uint2*>(lb);
}

// ---------------- kernel 3: x -> per-head K-major hi/lo, [h][n][p'] ----------------
__global__ __launch_bounds__(256) void xsplit_kernel(const float* __restrict__ x) {
    __shared__ float s[64][65];
    const int t = threadIdx.x;
    const int c0 = blockIdx.x * 64;
    const int p0 = blockIdx.y * 64;
    const int b  = blockIdx.z;

#pragma unroll
    for (int it = 0; it < 16; it++) {
        int prow = it * 4 + (t >> 6);
        int cl   = t & 63;
        s[prow][cl] = x[((size_t)(b * SEQ) + p0 + prow) * CHAN + c0 + cl];
    }
    __syncthreads();

    const int cl = t >> 2;
    const int pq = t & 3;
    const int c  = c0 + cl;
    const int h  = c & 7;
    const int ch = c >> 3;
    const size_t base = ((size_t)(h * NPH) + b * 64 + ch) * SEQ + p0 + pq * 16;
    __align__(16) __nv_bfloat16 hb[16], lb[16];
#pragma unroll
    for (int k = 0; k < 16; k++) {
        float v = s[pq * 16 + k][cl];
        __nv_bfloat16 hi = __float2bfloat16(v);
        hb[k] = hi;
        lb[k] = __float2bfloat16(v - __bfloat162float(hi));
    }
    *reinterpret_cast<uint4*>(&g_xhi[base])     = *reinterpret_cast<uint4*>(hb);
    *reinterpret_cast<uint4*>(&g_xhi[base + 8]) = *reinterpret_cast<uint4*>(hb + 8);
    *reinterpret_cast<uint4*>(&g_xlo[base])     = *reinterpret_cast<uint4*>(lb);
    *reinterpret_cast<uint4*>(&g_xlo[base + 8]) = *reinterpret_cast<uint4*>(lb + 8);
}

// ---------------- kernel 4: HMMA GEMM, cp.async double-buffered ----------------
// CTA: (ptile 128, head, batch). Warps 4x2: each M=32, N=32, K=512 in 8 chunks.
// Per-stage smem: Ahi 16K | Alo 16K | Bhi 8K | Blo 8K = 48K; 2 stages = 96K dynamic.
#define AHI 0
#define ALO 16384
#define BHI 32768
#define BLO 40960
#define STAGE_BYTES 49152
#define GEMM_SMEM (2 * STAGE_BYTES)

__global__ __launch_bounds__(256, 2) void gemm_kernel(float* __restrict__ out) {
    extern __shared__ __align__(16) unsigned char sm[];
    const uint32_t sb0 = smem_u32(sm);
    const int tid  = threadIdx.x;
    const int lane = tid & 31;
    const int wid  = tid >> 5;
    const int wm   = wid & 3;       // m-group: 32 p rows
    const int wn   = wid >> 2;      // n-group: 32 ch cols
    const int p0 = blockIdx.x * 128;
    const int h  = blockIdx.y;
    const int b  = blockIdx.z;

    const __nv_bfloat16* gAhi = g_whi + ((size_t)h * SEQ + p0) * SEQ;
    const __nv_bfloat16* gAlo = g_wlo + ((size_t)h * SEQ + p0) * SEQ;
    const __nv_bfloat16* gBhi = g_xhi + ((size_t)h * NPH + b * 64) * SEQ;
    const __nv_bfloat16* gBlo = g_xlo + ((size_t)h * NPH + b * 64) * SEQ;

    // per-thread staging coordinates (16B granules)
    const int st_row_a = tid >> 3, st_c16 = tid & 7;         // A: rows tid/8+i*32
    const int st_soA = ((st_row_a * 8) + (st_c16 ^ (st_row_a & 7))) * 16;

    // stage one K-chunk (64 elems) into stage buffer s (0/1) via cp.async
    auto stage = [&](int ck, int s) {
        const int kb = ck * 64;
        const uint32_t dst = sb0 + s * STAGE_BYTES;
#pragma unroll
        for (int i = 0; i < 4; i++) {
            int row = st_row_a + i * 32;
            int so = ((row * 8) + (st_c16 ^ (row & 7))) * 16;
            CP_ASYNC16(dst + AHI + so, gAhi + (size_t)row * SEQ + kb + st_c16 * 8);
            CP_ASYNC16(dst + ALO + so, gAlo + (size_t)row * SEQ + kb + st_c16 * 8);
        }
#pragma unroll
        for (int i = 0; i < 2; i++) {
            int row = st_row_a + i * 32;
            int so = ((row * 8) + (st_c16 ^ (row & 7))) * 16;
            CP_ASYNC16(dst + BHI + so, gBhi + (size_t)row * SEQ + kb + st_c16 * 8);
            CP_ASYNC16(dst + BLO + so, gBlo + (size_t)row * SEQ + kb + st_c16 * 8);
        }
        CP_COMMIT();
    };

    // ldmatrix per-lane bases
    const int g  = lane >> 3, rr = lane & 7;
    const int a_row = wm * 32 + (g & 1) * 8 + rr;    // + mi*16
    const int a_cg  = g >> 1;                        // + 2*ks
    const int b_row = wn * 32 + (g >> 1) * 8 + rr;   // + nt*16
    const int b_cg  = g & 1;                         // + 2*ks

    float acc[2][4][4];
#pragma unroll
    for (int mi = 0; mi < 2; mi++)
#pragma unroll
        for (int ni = 0; ni < 4; ni++)
#pragma unroll
            for (int e = 0; e < 4; e++) acc[mi][ni][e] = 0.f;

    stage(0, 0);

    for (int ck = 0; ck < 8; ck++) {
        if (ck + 1 < 8) stage(ck + 1, (ck + 1) & 1);
        if (ck + 1 < 8) { CP_WAIT(1); } else { CP_WAIT(0); }
        __syncthreads();

        const uint32_t sb = sb0 + (ck & 1) * STAGE_BYTES;
#pragma unroll
        for (int ks = 0; ks < 4; ks++) {
            uint32_t Ah[2][4], Al[2][4], Bh[2][4], Bl[2][4];
#pragma unroll
            for (int mi = 0; mi < 2; mi++) {
                int row = a_row + mi * 16;
                int c16 = 2 * ks + a_cg;
                uint32_t ad = sb + (uint32_t)((row * 8 + (c16 ^ (row & 7))) * 16);
                ldsm_x4(Ah[mi], ad + AHI);
                ldsm_x4(Al[mi], ad + ALO);
            }
#pragma unroll
            for (int nt = 0; nt < 2; nt++) {
                int row = b_row + nt * 16;
                int c16 = 2 * ks + b_cg;
                uint32_t bd = sb + (uint32_t)((row * 8 + (c16 ^ (row & 7))) * 16);
                ldsm_x4(Bh[nt], bd + BHI);
                ldsm_x4(Bl[nt], bd + BLO);
            }
#pragma unroll
            for (int mi = 0; mi < 2; mi++)
#pragma unroll
                for (int ni = 0; ni < 4; ni++) {
                    const uint32_t* bh = &Bh[ni >> 1][(ni & 1) * 2];
                    const uint32_t* bl = &Bl[ni >> 1][(ni & 1) * 2];
                    mma_bf16(acc[mi][ni], Ah[mi], bh);  // hi*hi
                    mma_bf16(acc[mi][ni], Ah[mi], bl);  // hi*lo
                    mma_bf16(acc[mi][ni], Al[mi], bh);  // lo*hi
                }
        }
        __syncthreads();   // protect stage buffer (ck&1) before restaging at ck+2
    }

    // epilogue: C frag (row = lane/4 (+8), col = 2*(lane%4)+{0,1}) -> out[b][p][ch*8+h]
    const int prb = p0 + wm * 32 + (lane >> 2);
    const int chb = wn * 32 + 2 * (lane & 3);
    float* ob = out + (size_t)b * SEQ * CHAN + h;
#pragma unroll
    for (int mi = 0; mi < 2; mi++)
#pragma unroll
        for (int ni = 0; ni < 4; ni++)
#pragma unroll
            for (int e = 0; e < 4; e++) {
                int p  = prb + mi * 16 + (e >> 1) * 8;
                int ch = chb + ni * 8 + (e & 1);
                ob[(size_t)p * CHAN + ch * NH] = acc[mi][ni][e];
            }
}

// ---------------- launch ----------------
extern "C" void kernel_launch(void* const* d_in, const int* in_sizes, int n_in,
                              void* d_out, int out_size) {
    const float* x = nullptr;
    const float* basis = nullptr;
    const float* kern = nullptr;
    for (int i = 0; i < n_in; i++) {
        if (in_sizes[i] == BATCH * SEQ * CHAN)      x     = (const float*)d_in[i];
        else if (in_sizes[i] == SEQ * 24)           basis = (const float*)d_in[i];
        else if (in_sizes[i] == 24 * NH)            kern  = (const float*)d_in[i];
    }
    float* out = (float*)d_out;

    cudaFuncSetAttribute(gemm_kernel,
                         cudaFuncAttributeMaxDynamicSharedMemorySize, GEMM_SMEM);

    wtab_kernel<<<1, 512>>>(basis, kern);
    wsplit_kernel<<<2048, 256>>>();
    xsplit_kernel<<<dim3(8, 8, 32), 256>>>(x);
    gemm_kernel<<<dim3(4, NH, BATCH), 256, GEMM_SMEM>>>(out);
}

// round 8
// speedup vs baseline: 4.7901x; 1.5332x over previous
#include <cuda_runtime.h>
#include <cuda_bf16.h>
#include <cuda_fp16.h>
#include <cstdint>

#define SEQ 512
#define CHAN 512
#define NH 8
#define BATCH 32
#define NPH 2048   // n per head = 32 batch * 64 ch

// ---------------- device globals (scratch; no allocs allowed) ----------------
__device__ __align__(16) float g_wtab[SEQ * NH];          // [delta][h]
__device__ __align__(16) __half g_wh[NH * SEQ * SEQ];     // [h][p][p'] 4MB fp16
__device__ __align__(16) __half g_xh[NH * NPH * SEQ];     // [h][n][p'] 16MB fp16

// ---------------- helpers ----------------
__device__ __forceinline__ uint32_t smem_u32(const void* p) {
    uint32_t a;
    asm("{ .reg .u64 t; cvta.to.shared.u64 t, %1; cvt.u32.u64 %0, t; }" : "=r"(a) : "l"(p));
    return a;
}
__device__ __forceinline__ void ldsm_x4(uint32_t r[4], uint32_t addr) {
    asm volatile("ldmatrix.sync.aligned.m8n8.x4.shared.b16 {%0,%1,%2,%3}, [%4];"
                 : "=r"(r[0]), "=r"(r[1]), "=r"(r[2]), "=r"(r[3]) : "r"(addr));
}
__device__ __forceinline__ void mma_fp16(float c[4], const uint32_t a[4],
                                         const uint32_t* b) {
    asm volatile("mma.sync.aligned.m16n8k16.row.col.f32.f16.f16.f32 "
                 "{%0,%1,%2,%3}, {%4,%5,%6,%7}, {%8,%9}, {%0,%1,%2,%3};"
                 : "+f"(c[0]), "+f"(c[1]), "+f"(c[2]), "+f"(c[3])
                 : "r"(a[0]), "r"(a[1]), "r"(a[2]), "r"(a[3]), "r"(b[0]), "r"(b[1]));
}
#define CP_ASYNC16(dst, src) \
    asm volatile("cp.async.cg.shared.global [%0], [%1], 16;" \
                 :: "r"(dst), "l"(src) : "memory")
#define CP_COMMIT() asm volatile("cp.async.commit_group;" ::: "memory")
#define CP_WAIT(n)  asm volatile("cp.async.wait_group %0;" :: "n"(n) : "memory")

// ---------------- kernel 1: wtab = basis @ kernel ----------------
__global__ void wtab_kernel(const float* __restrict__ basis,
                            const float* __restrict__ kern) {
    __shared__ float sk[24 * NH];
    int t = threadIdx.x;
    if (t < 24 * NH) sk[t] = kern[t];
    __syncthreads();
    if (t < SEQ) {
        float acc[NH];
#pragma unroll
        for (int h = 0; h < NH; h++) acc[h] = 0.f;
#pragma unroll
        for (int s = 0; s < 24; s++) {
            float bv = basis[t * 24 + s];
#pragma unroll
            for (int h = 0; h < NH; h++) acc[h] = fmaf(bv, sk[s * NH + h], acc[h]);
        }
#pragma unroll
        for (int h = 0; h < NH; h++) g_wtab[t * NH + h] = acc[h];
    }
}

__device__ __forceinline__ int delta_idx(int pp, int pr) {
    int d0 = (pp - pr) & 7;
    int d1 = ((pp >> 3) - (pr >> 3)) & 7;
    int d2 = ((pp >> 6) - (pr >> 6)) & 7;
    return (d2 << 6) | (d1 << 3) | d0;
}

// ---------------- kernel 2: materialize W_h fp16, [h][p][p'] ----------------
__global__ void wsplit_kernel() {
    int idx4 = (blockIdx.x * 256 + threadIdx.x) * 4;   // 8*512*512 total
    int h = idx4 >> 18;
    int rem = idx4 & 0x3FFFF;
    int p = rem >> 9;
    int pp0 = rem & 511;
    __align__(8) __half hb[4];
#pragma unroll
    for (int j = 0; j < 4; j++)
        hb[j] = __float2half(g_wtab[delta_idx(pp0 + j, p) * NH + h]);
    *reinterpret_cast<uint2*>(&g_wh[idx4]) = *reinterpret_cast<uint2*>(hb);
}

// ---------------- kernel 3: x -> per-head K-major fp16, [h][n][p'] ----------------
__global__ __launch_bounds__(256) void xsplit_kernel(const float* __restrict__ x) {
    __shared__ float s[64][65];
    const int t = threadIdx.x;
    const int c0 = blockIdx.x * 64;
    const int p0 = blockIdx.y * 64;
    const int b  = blockIdx.z;

#pragma unroll
    for (int it = 0; it < 16; it++) {
        int prow = it * 4 + (t >> 6);
        int cl   = t & 63;
        s[prow][cl] = x[((size_t)(b * SEQ) + p0 + prow) * CHAN + c0 + cl];
    }
    __syncthreads();

    const int cl = t >> 2;
    const int pq = t & 3;
    const int c  = c0 + cl;
    const int h  = c & 7;
    const int ch = c >> 3;
    const size_t base = ((size_t)(h * NPH) + b * 64 + ch) * SEQ + p0 + pq * 16;
    __align__(16) __half hb[16];
#pragma unroll
    for (int k = 0; k < 16; k++)
        hb[k] = __float2half(s[pq * 16 + k][cl]);
    *reinterpret_cast<uint4*>(&g_xh[base])     = *reinterpret_cast<uint4*>(hb);
    *reinterpret_cast<uint4*>(&g_xh[base + 8]) = *reinterpret_cast<uint4*>(hb + 8);
}

// ---------------- kernel 4: fp16 HMMA GEMM, cp.async double-buffered ----------------
// CTA: M=128 (p), N=128 (n), K=512 in 8 chunks of 64. Warps 4x2, each 32x64.
// Per-stage smem: A 16K | B 16K = 32K; 2 stages = 64K dynamic.
#define A_OFF 0
#define B_OFF 16384
#define STAGE_BYTES 32768
#define GEMM_SMEM (2 * STAGE_BYTES)

__global__ __launch_bounds__(256, 2) void gemm_kernel(float* __restrict__ out) {
    extern __shared__ __align__(16) unsigned char sm[];
    const uint32_t sb0 = smem_u32(sm);
    const int tid  = threadIdx.x;
    const int lane = tid & 31;
    const int wid  = tid >> 5;
    const int wm   = wid & 3;       // m-group: 32 p rows
    const int wn   = wid >> 2;      // n-group: 64 n cols
    const int p0 = blockIdx.x * 128;
    const int n0 = blockIdx.y * 128;
    const int h  = blockIdx.z;

    const __half* gA = g_wh + ((size_t)h * SEQ + p0) * SEQ;
    const __half* gB = g_xh + ((size_t)h * NPH + n0) * SEQ;

    // stage one K-chunk (64 halves) into stage buffer s via cp.async
    auto stage = [&](int ck, int s) {
        const int kb = ck * 64;
        const uint32_t dst = sb0 + s * STAGE_BYTES;
#pragma unroll
        for (int i = 0; i < 4; i++) {
            int id = tid + i * 256;          // 1024 granules each
            int row = id >> 3, c16 = id & 7;
            int so = ((row * 8) + (c16 ^ (row & 7))) * 16;
            CP_ASYNC16(dst + A_OFF + so, gA + (size_t)row * SEQ + kb + c16 * 8);
            CP_ASYNC16(dst + B_OFF + so, gB + (size_t)row * SEQ + kb + c16 * 8);
        }
        CP_COMMIT();
    };

    // ldmatrix per-lane bases
    const int g  = lane >> 3, rr = lane & 7;
    const int a_row = wm * 32 + (g & 1) * 8 + rr;    // + mi*16
    const int a_cg  = g >> 1;                        // + 2*ks
    const int b_row = wn * 64 + (g >> 1) * 8 + rr;   // + nt*16
    const int b_cg  = g & 1;                         // + 2*ks

    float acc[2][8][4];
#pragma unroll
    for (int mi = 0; mi < 2; mi++)
#pragma unroll
        for (int ni = 0; ni < 8; ni++)
#pragma unroll
            for (int e = 0; e < 4; e++) acc[mi][ni][e] = 0.f;

    stage(0, 0);

    for (int ck = 0; ck < 8; ck++) {
        if (ck + 1 < 8) { stage(ck + 1, (ck + 1) & 1); CP_WAIT(1); }
        else           { CP_WAIT(0); }
        __syncthreads();

        const uint32_t sb = sb0 + (ck & 1) * STAGE_BYTES;
#pragma unroll
        for (int ks = 0; ks < 4; ks++) {
            uint32_t Af[2][4], Bf[4][4];
#pragma unroll
            for (int mi = 0; mi < 2; mi++) {
                int row = a_row + mi * 16;
                int c16 = 2 * ks + a_cg;
                ldsm_x4(Af[mi], sb + A_OFF + (uint32_t)((row * 8 + (c16 ^ (row & 7))) * 16));
            }
#pragma unroll
            for (int nt = 0; nt < 4; nt++) {
                int row = b_row + nt * 16;
                int c16 = 2 * ks + b_cg;
                ldsm_x4(Bf[nt], sb + B_OFF + (uint32_t)((row * 8 + (c16 ^ (row & 7))) * 16));
            }
#pragma unroll
            for (int mi = 0; mi < 2; mi++)
#pragma unroll
                for (int ni = 0; ni < 8; ni++)
                    mma_fp16(acc[mi][ni], Af[mi], &Bf[ni >> 1][(ni & 1) * 2]);
        }
        __syncthreads();   // protect stage buffer before restaging
    }

    // epilogue: C frag -> out[b][p][ch*8+h], n = n0 + local, b = n>>6, ch = n&63
    const int prb = p0 + wm * 32 + (lane >> 2);
    const int nlb = n0 + wn * 64 + 2 * (lane & 3);
#pragma unroll
    for (int mi = 0; mi < 2; mi++)
#pragma unroll
        for (int ni = 0; ni < 8; ni++)
#pragma unroll
            for (int e = 0; e < 4; e++) {
                int p = prb + mi * 16 + (e >> 1) * 8;
                int n = nlb + ni * 8 + (e & 1);
                int b = n >> 6, ch = n & 63;
                out[((size_t)(b * SEQ) + p) * CHAN + ch * NH + h] = acc[mi][ni][e];
            }
}

// ---------------- launch ----------------
extern "C" void kernel_launch(void* const* d_in, const int* in_sizes, int n_in,
                              void* d_out, int out_size) {
    const float* x = nullptr;
    const float* basis = nullptr;
    const float* kern = nullptr;
    for (int i = 0; i < n_in; i++) {
        if (in_sizes[i] == BATCH * SEQ * CHAN)      x     = (const float*)d_in[i];
        else if (in_sizes[i] == SEQ * 24)           basis = (const float*)d_in[i];
        else if (in_sizes[i] == 24 * NH)            kern  = (const float*)d_in[i];
    }
    float* out = (float*)d_out;

    cudaFuncSetAttribute(gemm_kernel,
                         cudaFuncAttributeMaxDynamicSharedMemorySize, GEMM_SMEM);

    wtab_kernel<<<1, 512>>>(basis, kern);
    wsplit_kernel<<<2048, 256>>>();
    xsplit_kernel<<<dim3(8, 8, 32), 256>>>(x);
    gemm_kernel<<<dim3(4, 16, NH), 256, GEMM_SMEM>>>(out);
}

// round 9
// speedup vs baseline: 5.0618x; 1.0567x over previous
#include <cuda_runtime.h>
#include <cuda_fp16.h>
#include <cstdint>

#define SEQ 512
#define CHAN 512
#define NH 8
#define BATCH 32
#define NPH 2048          // n per head = 32 batch * 64 ch
#define TILE_B 16384      // one chunk tile: 128 rows x 128 bytes (swizzled)
#define NSTAGE 3
#define STAGE_BYTES (2 * TILE_B)
#define MBAR_OFF (NSTAGE * STAGE_BYTES)
#define GEMM_SMEM (MBAR_OFF + 64)

// ---------------- device globals (scratch; no allocs allowed) ----------------
__device__ __align__(16) float g_wtab[SEQ * NH];                       // [delta][h]
// blocked + pre-swizzled scratch: one 16KB tile per (h, tile, ck)
__device__ __align__(16) unsigned char g_wh[NH * 4 * 8 * TILE_B];      // 4MB
__device__ __align__(16) unsigned char g_xh[NH * 16 * 8 * TILE_B];     // 16MB

// ---------------- helpers ----------------
__device__ __forceinline__ uint32_t smem_u32(const void* p) {
    uint32_t a;
    asm("{ .reg .u64 t; cvta.to.shared.u64 t, %1; cvt.u32.u64 %0, t; }" : "=r"(a) : "l"(p));
    return a;
}
__device__ __forceinline__ void ldsm_x4(uint32_t r[4], uint32_t addr) {
    asm volatile("ldmatrix.sync.aligned.m8n8.x4.shared.b16 {%0,%1,%2,%3}, [%4];"
                 : "=r"(r[0]), "=r"(r[1]), "=r"(r[2]), "=r"(r[3]) : "r"(addr));
}
__device__ __forceinline__ void mma_fp16(float c[4], const uint32_t a[4],
                                         const uint32_t* b) {
    asm volatile("mma.sync.aligned.m16n8k16.row.col.f32.f16.f16.f32 "
                 "{%0,%1,%2,%3}, {%4,%5,%6,%7}, {%8,%9}, {%0,%1,%2,%3};"
                 : "+f"(c[0]), "+f"(c[1]), "+f"(c[2]), "+f"(c[3])
                 : "r"(a[0]), "r"(a[1]), "r"(a[2]), "r"(a[3]), "r"(b[0]), "r"(b[1]));
}
#define MB_INIT(mb, cnt) \
    asm volatile("mbarrier.init.shared.b64 [%0], %1;" \
                 :: "r"((uint32_t)(mb)), "r"((uint32_t)(cnt)) : "memory")
#define MB_EXPECT_TX(mb, bytes) \
    asm volatile("mbarrier.arrive.expect_tx.shared.b64 _, [%0], %1;" \
                 :: "r"((uint32_t)(mb)), "r"((uint32_t)(bytes)) : "memory")
#define MB_WAIT_PARITY(mb, par) do {                                            \
    uint32_t _m = (uint32_t)(mb), _p = (uint32_t)(par), _d;                     \
    asm volatile("{\n\t.reg .pred p;\n\t"                                       \
        "mbarrier.try_wait.parity.acquire.cta.shared::cta.b64 p, [%1], %2;\n\t" \
        "selp.b32 %0, 1, 0, p;\n\t}" : "=r"(_d) : "r"(_m), "r"(_p) : "memory"); \
    if (!_d) {                                                                  \
        asm volatile("{\n\t.reg .pred P1;\n\t"                                  \
            "WL_%=:\n\t"                                                        \
            "mbarrier.try_wait.parity.acquire.cta.shared::cta.b64 P1, [%0], %1, 0x989680;\n\t" \
            "@P1 bra.uni WD_%=;\n\t"                                            \
            "bra.uni WL_%=;\n\t"                                                \
            "WD_%=:\n\t}" :: "r"(_m), "r"(_p) : "memory");                      \
    }                                                                           \
} while (0)
#define CP_BULK(dst, src, sz, mb) \
    asm volatile("cp.async.bulk.shared::cluster.global.mbarrier::complete_tx::bytes " \
                 "[%0], [%1], %2, [%3];" \
                 :: "r"((uint32_t)(dst)), "l"(src), "r"((uint32_t)(sz)), \
                    "r"((uint32_t)(mb)) : "memory")

// swizzled byte offset of granule (row, c16) inside a 16KB tile
__device__ __forceinline__ int sw_off(int row, int c16) {
    return (row * 8 + (c16 ^ (row & 7))) * 16;
}

// ---------------- kernel 1: wtab = basis @ kernel ----------------
__global__ void wtab_kernel(const float* __restrict__ basis,
                            const float* __restrict__ kern) {
    __shared__ float sk[24 * NH];
    int t = threadIdx.x;
    if (t < 24 * NH) sk[t] = kern[t];
    __syncthreads();
    if (t < SEQ) {
        float acc[NH];
#pragma unroll
        for (int h = 0; h < NH; h++) acc[h] = 0.f;
#pragma unroll
        for (int s = 0; s < 24; s++) {
            float bv = basis[t * 24 + s];
#pragma unroll
            for (int h = 0; h < NH; h++) acc[h] = fmaf(bv, sk[s * NH + h], acc[h]);
        }
#pragma unroll
        for (int h = 0; h < NH; h++) g_wtab[t * NH + h] = acc[h];
    }
}

__device__ __forceinline__ int delta_idx(int pp, int pr) {
    int d0 = (pp - pr) & 7;
    int d1 = ((pp >> 3) - (pr >> 3)) & 7;
    int d2 = ((pp >> 6) - (pr >> 6)) & 7;
    return (d2 << 6) | (d1 << 3) | d0;
}

// ---------------- kernel 2: W -> blocked swizzled fp16 tiles ----------------
// granule id -> (h, pt, ck, row, c16); 8 halves per granule
__global__ void wsplit_kernel() {
    int gid = blockIdx.x * 256 + threadIdx.x;   // 262144 granules
    int c16 = gid & 7;
    int row = (gid >> 3) & 127;
    int ck  = (gid >> 10) & 7;
    int pt  = (gid >> 13) & 3;
    int h   = gid >> 15;
    int p   = pt * 128 + row;
    __align__(16) __half hb[8];
#pragma unroll
    for (int j = 0; j < 8; j++) {
        int pp = ck * 64 + c16 * 8 + j;
        hb[j] = __float2half(g_wtab[delta_idx(pp, p) * NH + h]);
    }
    size_t off = ((size_t)((h * 4 + pt) * 8 + ck)) * TILE_B + sw_off(row, c16);
    *reinterpret_cast<uint4*>(g_wh + off) = *reinterpret_cast<uint4*>(hb);
}

// ---------------- kernel 3: x -> blocked swizzled fp16 tiles ----------------
__global__ __launch_bounds__(256) void xsplit_kernel(const float* __restrict__ x) {
    __shared__ float s[64][65];
    const int t = threadIdx.x;
    const int c0 = blockIdx.x * 64;
    const int p0 = blockIdx.y * 64;
    const int b  = blockIdx.z;
    const int ck = blockIdx.y;      // 64 p' per ck chunk

#pragma unroll
    for (int it = 0; it < 16; it++) {
        int prow = it * 4 + (t >> 6);
        int cl   = t & 63;
        s[prow][cl] = x[((size_t)(b * SEQ) + p0 + prow) * CHAN + c0 + cl];
    }
    __syncthreads();

    const int cl = t >> 2;          // c local
    const int pq = t & 3;           // 16 p' each
    const int c  = c0 + cl;
    const int h  = c & 7;
    const int ch = c >> 3;
    const int n  = b * 64 + ch;
    const int nt = n >> 7;
    const int nrow = n & 127;
    const size_t tb = ((size_t)((h * 16 + nt) * 8 + ck)) * TILE_B;

#pragma unroll
    for (int g = 0; g < 2; g++) {
        int c16 = pq * 2 + g;
        __align__(16) __half hb[8];
#pragma unroll
        for (int j = 0; j < 8; j++)
            hb[j] = __float2half(s[c16 * 8 + j][cl]);
        *reinterpret_cast<uint4*>(g_xh + tb + sw_off(nrow, c16)) =
            *reinterpret_cast<uint4*>(hb);
    }
}

// ---------------- kernel 4: fp16 HMMA GEMM, cp.async.bulk 3-stage ----------------
// CTA: M=128 (p), N=128 (n), K=512 in 8 chunks. Warps 4x2, each 32x64.
__global__ __launch_bounds__(256, 2) void gemm_kernel(float* __restrict__ out) {
    extern __shared__ __align__(16) unsigned char sm[];
    const uint32_t sb0 = smem_u32(sm);
    const int tid  = threadIdx.x;
    const int lane = tid & 31;
    const int wid  = tid >> 5;
    const int wm   = wid & 3;       // m-group: 32 p rows
    const int wn   = wid >> 2;      // n-group: 64 n cols
    const int pt = blockIdx.x, nt = blockIdx.y, h = blockIdx.z;
    const int p0 = pt * 128;
    const int n0 = nt * 128;

    const unsigned char* gA = g_wh + ((size_t)((h * 4 + pt) * 8)) * TILE_B;
    const unsigned char* gB = g_xh + ((size_t)((h * 16 + nt) * 8)) * TILE_B;

    if (tid == 0) {
#pragma unroll
        for (int st = 0; st < NSTAGE; st++) MB_INIT(sb0 + MBAR_OFF + st * 8, 1);
    }
    __syncthreads();
    if (tid == 0) {
#pragma unroll
        for (int st = 0; st < NSTAGE; st++) {
            uint32_t mb = sb0 + MBAR_OFF + st * 8;
            MB_EXPECT_TX(mb, STAGE_BYTES);
            CP_BULK(sb0 + st * STAGE_BYTES,          gA + st * TILE_B, TILE_B, mb);
            CP_BULK(sb0 + st * STAGE_BYTES + TILE_B, gB + st * TILE_B, TILE_B, mb);
        }
    }

    // ldmatrix per-lane bases
    const int g  = lane >> 3, rr = lane & 7;
    const int a_row = wm * 32 + (g & 1) * 8 + rr;    // + mi*16
    const int a_cg  = g >> 1;                        // + 2*ks
    const int b_row = wn * 64 + (g >> 1) * 8 + rr;   // + nt*16
    const int b_cg  = g & 1;                         // + 2*ks

    float acc[2][8][4];
#pragma unroll
    for (int mi = 0; mi < 2; mi++)
#pragma unroll
        for (int ni = 0; ni < 8; ni++)
#pragma unroll
            for (int e = 0; e < 4; e++) acc[mi][ni][e] = 0.f;

    int st = 0, par = 0;
#pragma unroll 1
    for (int ck = 0; ck < 8; ck++) {
        const uint32_t mb = sb0 + MBAR_OFF + st * 8;
        MB_WAIT_PARITY(mb, par);
        const uint32_t sb = sb0 + st * STAGE_BYTES;

#pragma unroll
        for (int ks = 0; ks < 4; ks++) {
            uint32_t Af[2][4], Bf[4][4];
#pragma unroll
            for (int mi = 0; mi < 2; mi++) {
                int row = a_row + mi * 16;
                int c16 = 2 * ks + a_cg;
                ldsm_x4(Af[mi], sb + (uint32_t)sw_off(row, c16));
            }
#pragma unroll
            for (int bt = 0; bt < 4; bt++) {
                int row = b_row + bt * 16;
                int c16 = 2 * ks + b_cg;
                ldsm_x4(Bf[bt], sb + TILE_B + (uint32_t)sw_off(row, c16));
            }
#pragma unroll
            for (int mi = 0; mi < 2; mi++)
#pragma unroll
                for (int ni = 0; ni < 8; ni++)
                    mma_fp16(acc[mi][ni], Af[mi], &Bf[ni >> 1][(ni & 1) * 2]);
        }
        __syncthreads();   // all warps done with this stage buffer

        if (tid == 0 && ck + NSTAGE < 8) {
            MB_EXPECT_TX(mb, STAGE_BYTES);
            CP_BULK(sb,          gA + (ck + NSTAGE) * TILE_B, TILE_B, mb);
            CP_BULK(sb + TILE_B, gB + (ck + NSTAGE) * TILE_B, TILE_B, mb);
        }
        if (++st == NSTAGE) { st = 0; par ^= 1; }
    }

    // epilogue: C frag -> out[b][p][ch*8+h], n = n0 + local, b = n>>6, ch = n&63
    const int prb = p0 + wm * 32 + (lane >> 2);
    const int nlb = n0 + wn * 64 + 2 * (lane & 3);
#pragma unroll
    for (int mi = 0; mi < 2; mi++)
#pragma unroll
        for (int ni = 0; ni < 8; ni++)
#pragma unroll
            for (int e = 0; e < 4; e++) {
                int p = prb + mi * 16 + (e >> 1) * 8;
                int n = nlb + ni * 8 + (e & 1);
                int b = n >> 6, ch = n & 63;
                out[((size_t)(b * SEQ) + p) * CHAN + ch * NH + h] = acc[mi][ni][e];
            }
}

// ---------------- launch ----------------
extern "C" void kernel_launch(void* const* d_in, const int* in_sizes, int n_in,
                              void* d_out, int out_size) {
    const float* x = nullptr;
    const float* basis = nullptr;
    const float* kern = nullptr;
    for (int i = 0; i < n_in; i++) {
        if (in_sizes[i] == BATCH * SEQ * CHAN)      x     = (const float*)d_in[i];
        else if (in_sizes[i] == SEQ * 24)           basis = (const float*)d_in[i];
        else if (in_sizes[i] == 24 * NH)            kern  = (const float*)d_in[i];
    }
    float* out = (float*)d_out;

    cudaFuncSetAttribute(gemm_kernel,
                         cudaFuncAttributeMaxDynamicSharedMemorySize, GEMM_SMEM);

    wtab_kernel<<<1, 512>>>(basis, kern);
    wsplit_kernel<<<1024, 256>>>();
    xsplit_kernel<<<dim3(8, 8, 32), 256>>>(x);
    gemm_kernel<<<dim3(4, 16, NH), 256, GEMM_SMEM>>>(out);
}

// round 11
// speedup vs baseline: 5.1949x; 1.0263x over previous
#include <cuda_runtime.h>
#include <cuda_fp16.h>
#include <cstdint>

#define SEQ 512
#define CHAN 512
#define NH 8
#define BATCH 32
#define NPH 2048          // n per head = 32 batch * 64 ch
#define TILE_B 16384      // one chunk tile: 128 rows x 128 bytes (swizzled)
#define NSTAGE 3
#define STAGE_BYTES (2 * TILE_B)
#define MBAR_OFF (NSTAGE * STAGE_BYTES)
#define GEMM_SMEM (MBAR_OFF + 64)

// ---------------- device globals (scratch; no allocs allowed) ----------------
__device__ __align__(16) float g_wtab[SEQ * NH];                       // [delta][h]
__device__ __align__(16) unsigned char g_wh[NH * 4 * 8 * TILE_B];      // 4MB swizzled tiles
__device__ __align__(16) unsigned char g_xh[NH * 16 * 8 * TILE_B];     // 16MB swizzled tiles
__device__ __align__(16) float g_outT[NH * NPH * SEQ];                 // [h][n][p] 33.5MB

// ---------------- helpers ----------------
__device__ __forceinline__ uint32_t smem_u32(const void* p) {
    uint32_t a;
    asm("{ .reg .u64 t; cvta.to.shared.u64 t, %1; cvt.u32.u64 %0, t; }" : "=r"(a) : "l"(p));
    return a;
}
__device__ __forceinline__ void ldsm_x4(uint32_t r[4], uint32_t addr) {
    asm volatile("ldmatrix.sync.aligned.m8n8.x4.shared.b16 {%0,%1,%2,%3}, [%4];"
                 : "=r"(r[0]), "=r"(r[1]), "=r"(r[2]), "=r"(r[3]) : "r"(addr));
}
__device__ __forceinline__ void mma_fp16(float c[4], const uint32_t a[4],
                                         const uint32_t* b) {
    asm volatile("mma.sync.aligned.m16n8k16.row.col.f32.f16.f16.f32 "
                 "{%0,%1,%2,%3}, {%4,%5,%6,%7}, {%8,%9}, {%0,%1,%2,%3};"
                 : "+f"(c[0]), "+f"(c[1]), "+f"(c[2]), "+f"(c[3])
                 : "r"(a[0]), "r"(a[1]), "r"(a[2]), "r"(a[3]), "r"(b[0]), "r"(b[1]));
}
#define MB_INIT(mb, cnt) \
    asm volatile("mbarrier.init.shared.b64 [%0], %1;" \
                 :: "r"((uint32_t)(mb)), "r"((uint32_t)(cnt)) : "memory")
#define MB_EXPECT_TX(mb, bytes) \
    asm volatile("mbarrier.arrive.expect_tx.shared.b64 _, [%0], %1;" \
                 :: "r"((uint32_t)(mb)), "r"((uint32_t)(bytes)) : "memory")
#define MB_WAIT_PARITY(mb, par) do {                                            \
    uint32_t _m = (uint32_t)(mb), _p = (uint32_t)(par), _d;                     \
    asm volatile("{\n\t.reg .pred p;\n\t"                                       \
        "mbarrier.try_wait.parity.acquire.cta.shared::cta.b64 p, [%1], %2;\n\t" \
        "selp.b32 %0, 1, 0, p;\n\t}" : "=r"(_d) : "r"(_m), "r"(_p) : "memory"); \
    if (!_d) {                                                                  \
        asm volatile("{\n\t.reg .pred P1;\n\t"                                  \
            "WL_%=:\n\t"                                                        \
            "mbarrier.try_wait.parity.acquire.cta.shared::cta.b64 P1, [%0], %1, 0x989680;\n\t" \
            "@P1 bra.uni WD_%=;\n\t"                                            \
            "bra.uni WL_%=;\n\t"                                                \
            "WD_%=:\n\t}" :: "r"(_m), "r"(_p) : "memory");                      \
    }                                                                           \
} while (0)
#define CP_BULK(dst, src, sz, mb) \
    asm volatile("cp.async.bulk.shared::cluster.global.mbarrier::complete_tx::bytes " \
                 "[%0], [%1], %2, [%3];" \
                 :: "r"((uint32_t)(dst)), "l"(src), "r"((uint32_t)(sz)), \
                    "r"((uint32_t)(mb)) : "memory")

// swizzled byte offset of granule (row, c16) inside a 16KB tile
__device__ __forceinline__ int sw_off(int row, int c16) {
    return (row * 8 + (c16 ^ (row & 7))) * 16;
}

// ---------------- kernel 1: wtab = basis @ kernel ----------------
__global__ void wtab_kernel(const float* __restrict__ basis,
                            const float* __restrict__ kern) {
    __shared__ float sk[24 * NH];
    int t = threadIdx.x;
    if (t < 24 * NH) sk[t] = kern[t];
    __syncthreads();
    if (t < SEQ) {
        float acc[NH];
#pragma unroll
        for (int h = 0; h < NH; h++) acc[h] = 0.f;
#pragma unroll
        for (int s = 0; s < 24; s++) {
            float bv = basis[t * 24 + s];
#pragma unroll
            for (int h = 0; h < NH; h++) acc[h] = fmaf(bv, sk[s * NH + h], acc[h]);
        }
#pragma unroll
        for (int h = 0; h < NH; h++) g_wtab[t * NH + h] = acc[h];
    }
}

__device__ __forceinline__ int delta_idx(int pp, int pr) {
    int d0 = (pp - pr) & 7;
    int d1 = ((pp >> 3) - (pr >> 3)) & 7;
    int d2 = ((pp >> 6) - (pr >> 6)) & 7;
    return (d2 << 6) | (d1 << 3) | d0;
}

// ---------------- kernel 2: W -> blocked swizzled fp16 tiles ----------------
__global__ void wsplit_kernel() {
    int gid = blockIdx.x * 256 + threadIdx.x;   // 262144 granules
    int c16 = gid & 7;
    int row = (gid >> 3) & 127;
    int ck  = (gid >> 10) & 7;
    int pt  = (gid >> 13) & 3;
    int h   = gid >> 15;
    int p   = pt * 128 + row;
    __align__(16) __half hb[8];
#pragma unroll
    for (int j = 0; j < 8; j++) {
        int pp = ck * 64 + c16 * 8 + j;
        hb[j] = __float2half(g_wtab[delta_idx(pp, p) * NH + h]);
    }
    size_t off = ((size_t)((h * 4 + pt) * 8 + ck)) * TILE_B + sw_off(row, c16);
    *reinterpret_cast<uint4*>(g_wh + off) = *reinterpret_cast<uint4*>(hb);
}

// ---------------- kernel 3: x -> blocked swizzled fp16 tiles ----------------
__global__ __launch_bounds__(256) void xsplit_kernel(const float* __restrict__ x) {
    __shared__ float s[64][65];
    const int t = threadIdx.x;
    const int c0 = blockIdx.x * 64;
    const int p0 = blockIdx.y * 64;
    const int b  = blockIdx.z;
    const int ck = blockIdx.y;      // 64 p' per ck chunk

#pragma unroll
    for (int it = 0; it < 16; it++) {
        int prow = it * 4 + (t >> 6);
        int cl   = t & 63;
        s[prow][cl] = x[((size_t)(b * SEQ) + p0 + prow) * CHAN + c0 + cl];
    }
    __syncthreads();

    const int cl = t >> 2;          // c local
    const int pq = t & 3;           // 16 p' each
    const int c  = c0 + cl;
    const int h  = c & 7;
    const int ch = c >> 3;
    const int n  = b * 64 + ch;
    const int nt = n >> 7;
    const int nrow = n & 127;
    const size_t tb = ((size_t)((h * 16 + nt) * 8 + ck)) * TILE_B;

#pragma unroll
    for (int g = 0; g < 2; g++) {
        int c16 = pq * 2 + g;
        __align__(16) __half hb[8];
#pragma unroll
        for (int j = 0; j < 8; j++)
            hb[j] = __float2half(s[c16 * 8 + j][cl]);
        *reinterpret_cast<uint4*>(g_xh + tb + sw_off(nrow, c16)) =
            *reinterpret_cast<uint4*>(hb);
    }
}

// ---------------- kernel 4: fp16 HMMA GEMM (R9 sync structure) + transposed epilogue ----
// CTA: M=128 (p), N=128 (n), K=512 in 8 chunks. Warps 4x2, each 32x64.
__global__ __launch_bounds__(256, 2) void gemm_kernel() {
    extern __shared__ __align__(16) unsigned char sm[];
    const uint32_t sb0 = smem_u32(sm);
    const int tid  = threadIdx.x;
    const int lane = tid & 31;
    const int wid  = tid >> 5;
    const int wm   = wid & 3;       // m-group: 32 p rows
    const int wn   = wid >> 2;      // n-group: 64 n cols
    const int pt = blockIdx.x, nt = blockIdx.y, h = blockIdx.z;
    const int p0 = pt * 128;
    const int n0 = nt * 128;

    const unsigned char* gA = g_wh + ((size_t)((h * 4 + pt) * 8)) * TILE_B;
    const unsigned char* gB = g_xh + ((size_t)((h * 16 + nt) * 8)) * TILE_B;

    if (tid == 0) {
#pragma unroll
        for (int st = 0; st < NSTAGE; st++) MB_INIT(sb0 + MBAR_OFF + st * 8, 1);
    }
    __syncthreads();
    if (tid == 0) {
#pragma unroll
        for (int st = 0; st < NSTAGE; st++) {
            uint32_t mb = sb0 + MBAR_OFF + st * 8;
            MB_EXPECT_TX(mb, STAGE_BYTES);
            CP_BULK(sb0 + st * STAGE_BYTES,          gA + st * TILE_B, TILE_B, mb);
            CP_BULK(sb0 + st * STAGE_BYTES + TILE_B, gB + st * TILE_B, TILE_B, mb);
        }
    }

    // ldmatrix per-lane bases
    const int g  = lane >> 3, rr = lane & 7;
    const int a_row = wm * 32 + (g & 1) * 8 + rr;    // + mi*16
    const int a_cg  = g >> 1;                        // + 2*ks
    const int b_row = wn * 64 + (g >> 1) * 8 + rr;   // + bt*16
    const int b_cg  = g & 1;                         // + 2*ks

    float acc[2][8][4];
#pragma unroll
    for (int mi = 0; mi < 2; mi++)
#pragma unroll
        for (int ni = 0; ni < 8; ni++)
#pragma unroll
            for (int e = 0; e < 4; e++) acc[mi][ni][e] = 0.f;

    int st = 0, par = 0;
#pragma unroll 1
    for (int ck = 0; ck < 8; ck++) {
        const uint32_t mb = sb0 + MBAR_OFF + st * 8;
        MB_WAIT_PARITY(mb, par);
        const uint32_t sb = sb0 + st * STAGE_BYTES;

#pragma unroll
        for (int ks = 0; ks < 4; ks++) {
            uint32_t Af[2][4], Bf[4][4];
#pragma unroll
            for (int mi = 0; mi < 2; mi++) {
                int row = a_row + mi * 16;
                int c16 = 2 * ks + a_cg;
                ldsm_x4(Af[mi], sb + (uint32_t)sw_off(row, c16));
            }
#pragma unroll
            for (int bt = 0; bt < 4; bt++) {
                int row = b_row + bt * 16;
                int c16 = 2 * ks + b_cg;
                ldsm_x4(Bf[bt], sb + TILE_B + (uint32_t)sw_off(row, c16));
            }
#pragma unroll
            for (int mi = 0; mi < 2; mi++)
#pragma unroll
                for (int ni = 0; ni < 8; ni++)
                    mma_fp16(acc[mi][ni], Af[mi], &Bf[ni >> 1][(ni & 1) * 2]);
        }
        __syncthreads();   // all warps done with this stage buffer

        if (tid == 0 && ck + NSTAGE < 8) {
            MB_EXPECT_TX(mb, STAGE_BYTES);
            CP_BULK(sb,          gA + (ck + NSTAGE) * TILE_B, TILE_B, mb);
            CP_BULK(sb + TILE_B, gB + (ck + NSTAGE) * TILE_B, TILE_B, mb);
        }
        if (++st == NSTAGE) { st = 0; par ^= 1; }
    }

    // ---- epilogue: smem transpose then coalesced 16B stores to g_outT[h][n][p] ----
    // (stage buffers fully consumed; safe to reuse sm. sf = 128*132*4 = 67.5KB < MBAR_OFF)
    float* sf = reinterpret_cast<float*>(sm);   // [128 n][132 pad] fp32
    {
        const int prl = wm * 32 + (lane >> 2);
        const int nll = wn * 64 + 2 * (lane & 3);
#pragma unroll
        for (int mi = 0; mi < 2; mi++)
#pragma unroll
            for (int ni = 0; ni < 8; ni++)
#pragma unroll
                for (int e = 0; e < 4; e++) {
                    int p_l = prl + mi * 16 + (e >> 1) * 8;
                    int n_l = nll + ni * 8 + (e & 1);
                    sf[n_l * 132 + p_l] = acc[mi][ni][e];
                }
    }
    __syncthreads();
    {
        const int n_l  = tid >> 1;
        const int half = tid & 1;
        const float4* src = reinterpret_cast<const float4*>(sf + n_l * 132 + half * 64);
        float4* dst = reinterpret_cast<float4*>(
            g_outT + ((size_t)(h * NPH) + n0 + n_l) * SEQ + p0 + half * 64);
#pragma unroll
        for (int i = 0; i < 16; i++) dst[i] = src[i];
    }
}

// ---------------- kernel 5: outT[h][n][p] -> out[b][p][c] ----------------
__global__ __launch_bounds__(256) void untranspose_kernel(float* __restrict__ out) {
    __shared__ float s[16][513];
    const int t = threadIdx.x;
    const int p0 = blockIdx.x * 16;
    const int b  = blockIdx.y;
    const int k  = t & 15;      // p_local
    const int rr = t >> 4;      // 0..15

    for (int it = 0; it < 32; it++) {
        int c = it * 16 + rr;                     // output channel 0..511
        int h = c & 7, ch = c >> 3;
        s[k][c] = g_outT[((size_t)(h * NPH) + b * 64 + ch) * SEQ + p0 + k];
    }
    __syncthreads();
#pragma unroll
    for (int p = 0; p < 16; p++) {
        float2 v = make_float2(s[p][2 * t], s[p][2 * t + 1]);
        *reinterpret_cast<float2*>(
            &out[((size_t)(b * SEQ) + p0 + p) * CHAN + 2 * t]) = v;
    }
}

// ---------------- launch ----------------
extern "C" void kernel_launch(void* const* d_in, const int* in_sizes, int n_in,
                              void* d_out, int out_size) {
    const float* x = nullptr;
    const float* basis = nullptr;
    const float* kern = nullptr;
    for (int i = 0; i < n_in; i++) {
        if (in_sizes[i] == BATCH * SEQ * CHAN)      x     = (const float*)d_in[i];
        else if (in_sizes[i] == SEQ * 24)           basis = (const float*)d_in[i];
        else if (in_sizes[i] == 24 * NH)            kern  = (const float*)d_in[i];
    }
    float* out = (float*)d_out;

    cudaFuncSetAttribute(gemm_kernel,
                         cudaFuncAttributeMaxDynamicSharedMemorySize, GEMM_SMEM);

    wtab_kernel<<<1, 512>>>(basis, kern);
    wsplit_kernel<<<1024, 256>>>();
    xsplit_kernel<<<dim3(8, 8, 32), 256>>>(x);
    gemm_kernel<<<dim3(4, 16, NH), 256, GEMM_SMEM>>>();
    untranspose_kernel<<<dim3(32, 32), 256>>>(out);
}